// round 17
// baseline (speedup 1.0000x reference)
#include <cuda_runtime.h>
#include <cuda_bf16.h>
#include <cstdint>

#define BB 4
#define CC 64
#define NT 32
#define NN 4096
#define GRID 512

typedef unsigned long long ull;

// ---- scratch ----------------------------------------------------------------
__device__ float g_upart[2 * BB * CC];   // [h][b*CC+c]
__device__ float g_vpart[2 * BB * CC];
__device__ unsigned g_bar;

// ---- dynamic smem map (bytes) ----------------------------------------------
#define SM_A     0        // [128 m][64 k] bf16 SW128  16384
#define SM_BHI   16384    // [64 k][32 n] bf16 (64B rows)  4096
#define SM_BLO   20480    //                                4096
// post-barrier overlays (A/B dead after MMA)
#define SM_DS0   0        // 64 o x 36 stride fp32      9216
#define SM_DS1   9216     //                            9216
#define SM_META  24576    // float4[32] {a, a*d, d*d}    512
#define SM_PS    25088    // 64 f
#define SM_QS    25344
#define SM_SC    25600
#define SM_SH    25856
#define SM_US    26112
#define SM_VS    26368
#define SM_PPART 26624    // 256 f
#define SM_QPART 27648    // 256 f
#define SM_RED   28672
#define SM_RED2  28704
#define SM_SSUM  28736
#define SM_TOTAL 28800

#define SWZ(o) ((o) ^ (((o) >> 3) & 0x70))

static __device__ __forceinline__ uint32_t smem_u32(const void* p) {
    uint32_t a;
    asm("{ .reg .u64 t; cvta.to.shared.u64 t, %1; cvt.u32.u64 %0, t; }" : "=r"(a) : "l"(p));
    return a;
}
static __device__ __forceinline__ void ldsm4(uint32_t* r, uint32_t addr) {
    asm volatile("ldmatrix.sync.aligned.m8n8.x4.shared.b16 {%0,%1,%2,%3}, [%4];"
        : "=r"(r[0]), "=r"(r[1]), "=r"(r[2]), "=r"(r[3]) : "r"(addr));
}
static __device__ __forceinline__ void ldsm4t(uint32_t* r, uint32_t addr) {
    asm volatile("ldmatrix.sync.aligned.m8n8.x4.trans.shared.b16 {%0,%1,%2,%3}, [%4];"
        : "=r"(r[0]), "=r"(r[1]), "=r"(r[2]), "=r"(r[3]) : "r"(addr));
}
static __device__ __forceinline__ void mma_bf16(float* d, const uint32_t* a,
                                                uint32_t b0, uint32_t b1) {
    asm volatile("mma.sync.aligned.m16n8k16.row.col.f32.bf16.bf16.f32 "
        "{%0,%1,%2,%3}, {%4,%5,%6,%7}, {%8,%9}, {%0,%1,%2,%3};"
        : "+f"(d[0]), "+f"(d[1]), "+f"(d[2]), "+f"(d[3])
        : "r"(a[0]), "r"(a[1]), "r"(a[2]), "r"(a[3]), "r"(b0), "r"(b1));
}

static __device__ __forceinline__ float relutanh(float x) {
    if (x <= 0.f) return 0.f;
    float e = __expf(-2.f * x);
    return __fdividef(1.f - e, 1.f + e);
}

static __device__ __forceinline__ void grid_barrier(int tid) {
    __threadfence();
    __syncthreads();
    if (tid == 0) {
        unsigned old = atomicAdd(&g_bar, 1u);
        unsigned target = (old & ~(unsigned)(GRID - 1)) + GRID;
        unsigned vcur;
        do { vcur = *(volatile unsigned*)&g_bar; } while ((int)(vcur - target) < 0);
        __threadfence();
    }
    __syncthreads();
}

static __device__ __forceinline__ ull pack_bf16x4(float a, float b, float c, float d) {
    __nv_bfloat162 lo2 = __float22bfloat162_rn(make_float2(a, b));
    __nv_bfloat162 hi2 = __float22bfloat162_rn(make_float2(c, d));
    uint32_t lo_u, hi_u;
    memcpy(&lo_u, &lo2, 4);
    memcpy(&hi_u, &hi2, 4);
    return (ull)lo_u | ((ull)hi_u << 32);
}

// -----------------------------------------------------------------------------
// grid=512, 256 threads, 4 blocks/SM (single wave: 512 <= 592; barrier-safe).
// blk -> b = blk>>7, tile = blk&127, n0 = tile*32; (c = tile>>1, h = tile&1)
// Pre-barrier : A=[W0;W1] bf16 + B=x [k][32n] hi/lo; BN fold; phase 1
//               (full w row -> a,S; half-row u/v partials -> g_upart; meta);
//               warp MMA (32 HMMA: A*(Bhi+Blo)).
// Post-barrier: bounce D via smem; aggregate u/v; p/q; combine + BN + ReLU.
// -----------------------------------------------------------------------------
__global__ void __launch_bounds__(256, 4) k_fused(
        const float* __restrict__ x,
        const float* __restrict__ w,
        const float* __restrict__ conv_w,
        const float* __restrict__ conv_b,
        const float* __restrict__ gamma,
        const float* __restrict__ beta,
        const float* __restrict__ mean,
        const float* __restrict__ var,
        float* __restrict__ out) {
    extern __shared__ char smem[];
    const uint32_t smb = smem_u32(smem);

    float4* meta = (float4*)(smem + SM_META);
    float* p_s   = (float*)(smem + SM_PS);
    float* q_s   = (float*)(smem + SM_QS);
    float* sc_s  = (float*)(smem + SM_SC);
    float* sh_s  = (float*)(smem + SM_SH);
    float* u_s   = (float*)(smem + SM_US);
    float* v_s   = (float*)(smem + SM_VS);
    float* ppart = (float*)(smem + SM_PPART);
    float* qpart = (float*)(smem + SM_QPART);
    float* red   = (float*)(smem + SM_RED);
    float* red2  = (float*)(smem + SM_RED2);

    const int tid = threadIdx.x;
    const int wid = tid >> 5, lid = tid & 31;
    const int blk = blockIdx.x;
    const int b = blk >> 7;
    const int tile = blk & 127;
    const int n0 = tile * NT;
    const int c = tile >> 1;
    const int h = tile & 1;

    // ---- stage A = [W0;W1] plain bf16, SW128, packed STS.64 ----
    {
        #pragma unroll
        for (int k = 0; k < 8; k++) {
            int i4 = tid + k * 256;              // 2048 float4
            int m = i4 >> 4, cb = (i4 & 15) * 4;
            const float* src = (m < CC) ? (conv_w + m * 128 + cb)
                                        : (conv_w + (m - CC) * 128 + CC + cb);
            float4 wv = *(const float4*)src;
            uint32_t off = (uint32_t)(m * 128 + cb * 2);
            *(ull*)(smem + SM_A + SWZ(off)) = pack_bf16x4(wv.x, wv.y, wv.z, wv.w);
        }
    }
    // ---- stage B[k=cc][n] = x[cc][n0+n] hi/lo (64B rows) ----
    {
        const int cc2 = tid >> 2;               // 0..63
        const int nc = (tid & 3) * 8;           // 0..24
        const float* xr = x + (size_t)(b * CC + cc2) * NN + n0 + nc;
        #pragma unroll
        for (int q4 = 0; q4 < 2; q4++) {
            float4 xv = *(const float4*)(xr + q4 * 4);
            __nv_bfloat16 h0 = __float2bfloat16(xv.x);
            __nv_bfloat16 h1 = __float2bfloat16(xv.y);
            __nv_bfloat16 h2 = __float2bfloat16(xv.z);
            __nv_bfloat16 h3 = __float2bfloat16(xv.w);
            float l0 = xv.x - __bfloat162float(h0);
            float l1 = xv.y - __bfloat162float(h1);
            float l2 = xv.z - __bfloat162float(h2);
            float l3 = xv.w - __bfloat162float(h3);
            uint32_t hlo, hhi;
            {
                __nv_bfloat162 t0 = __nv_bfloat162(h0, h1);
                __nv_bfloat162 t1 = __nv_bfloat162(h2, h3);
                memcpy(&hlo, &t0, 4);
                memcpy(&hhi, &t1, 4);
            }
            ull hp = (ull)hlo | ((ull)hhi << 32);
            ull lp = pack_bf16x4(l0, l1, l2, l3);
            uint32_t off = (uint32_t)(cc2 * 64 + (nc + q4 * 4) * 2);  // 8-aligned
            *(ull*)(smem + SM_BHI + SWZ(off)) = hp;
            *(ull*)(smem + SM_BLO + SWZ(off)) = lp;
        }
    }
    // ---- BN fold ----
    if (tid >= 128 && tid < 192) {
        int o = tid - 128;
        float sc = gamma[o] * rsqrtf(var[o] + 1e-5f);
        sc_s[o] = sc;
        sh_s[o] = fmaf(conv_b[o] - mean[o], sc, beta[o]);
    }

    // ---- phase 1: full w row -> a,S; half-row u/v partials; meta ----
    {
        const float4* w4  = (const float4*)(w + b * NN);
        const float4* x4u = (const float4*)(x + (size_t)(b * CC + c) * NN);
        float4 wv[4], xu[2];
        #pragma unroll
        for (int k = 0; k < 4; k++) wv[k] = w4[tid + k * 256];
        #pragma unroll
        for (int kk = 0; kk < 2; kk++) xu[kk] = x4u[tid + (2 * h + kk) * 256];

        float avr[16];
        float s = 0.f;
        #pragma unroll
        for (int k = 0; k < 4; k++) {
            avr[k*4+0] = relutanh(wv[k].x);
            avr[k*4+1] = relutanh(wv[k].y);
            avr[k*4+2] = relutanh(wv[k].z);
            avr[k*4+3] = relutanh(wv[k].w);
            s += avr[k*4+0] + avr[k*4+1] + avr[k*4+2] + avr[k*4+3];
        }
        #pragma unroll
        for (int off = 16; off; off >>= 1) s += __shfl_down_sync(0xffffffffu, s, off);
        if ((tid & 31) == 0) red[tid >> 5] = s;
        __syncthreads();
        if (tid == 0) {
            float t = 0.f;
            #pragma unroll
            for (int i = 0; i < 8; i++) t += red[i];
            *(float*)(smem + SM_SSUM) = t;
        }
        __syncthreads();
        const float S = *(float*)(smem + SM_SSUM);

        if (tid < NT) {
            float aa = relutanh(w[b * NN + n0 + tid]);
            float dd = rsqrtf(fmaf(aa, S, 1.f));
            meta[tid] = make_float4(aa, aa * dd, dd * dd, 0.f);
        }

        float su = 0.f, sv = 0.f;
        #pragma unroll
        for (int kk = 0; kk < 2; kk++) {
            const int k = 2 * h + kk;
            float d0 = rsqrtf(fmaf(avr[k*4+0], S, 1.f));
            float d1 = rsqrtf(fmaf(avr[k*4+1], S, 1.f));
            float d2 = rsqrtf(fmaf(avr[k*4+2], S, 1.f));
            float d3 = rsqrtf(fmaf(avr[k*4+3], S, 1.f));
            float t0 = xu[kk].x * avr[k*4+0], t1 = xu[kk].y * avr[k*4+1];
            float t2 = xu[kk].z * avr[k*4+2], t3 = xu[kk].w * avr[k*4+3];
            su += t0 + t1 + t2 + t3;
            sv += t0 * d0 + t1 * d1 + t2 * d2 + t3 * d3;
        }
        #pragma unroll
        for (int off = 16; off; off >>= 1) {
            su += __shfl_down_sync(0xffffffffu, su, off);
            sv += __shfl_down_sync(0xffffffffu, sv, off);
        }
        if ((tid & 31) == 0) { red[tid >> 5] = su; red2[tid >> 5] = sv; }
        __syncthreads();
        if (tid == 0) {
            float tu = 0.f, tv = 0.f;
            #pragma unroll
            for (int i = 0; i < 8; i++) { tu += red[i]; tv += red2[i]; }
            g_upart[h * BB * CC + b * CC + c] = tu;
            g_vpart[h * BB * CC + b * CC + c] = tv;
        }
    }
    __syncthreads();        // A, B, meta complete

    // ---- warp MMA: D = A*(Bhi + Blo) (B via ldmatrix.trans) ----
    const int m_base = wid * 16;
    const int lrow = lid & 15, lhalf = lid >> 4;
    float dacc[4][4];
    #pragma unroll
    for (int j = 0; j < 4; j++)
        #pragma unroll
        for (int i = 0; i < 4; i++) dacc[j][i] = 0.f;

    #pragma unroll
    for (int kc = 0; kc < 4; kc++) {
        const uint32_t arow = (uint32_t)((m_base + lrow) * 128 + kc * 32 + lhalf * 16);
        uint32_t af[4];
        ldsm4(af, smb + SM_A + SWZ(arow));
        #pragma unroll
        for (int g = 0; g < 2; g++) {
            const uint32_t brow = (uint32_t)((kc * 16 + lrow) * 64 + (g * 16 + lhalf * 8) * 2);
            uint32_t bh[4], bl[4];
            ldsm4t(bh, smb + SM_BHI + SWZ(brow));
            ldsm4t(bl, smb + SM_BLO + SWZ(brow));
            mma_bf16(dacc[2*g],   af, bh[0], bh[1]);
            mma_bf16(dacc[2*g+1], af, bh[2], bh[3]);
            mma_bf16(dacc[2*g],   af, bl[0], bl[1]);
            mma_bf16(dacc[2*g+1], af, bl[2], bl[3]);
        }
    }

    // ================= device-wide barrier =================
    grid_barrier(tid);

    // ---- bounce D (warps 0-3 -> ds0, 4-7 -> ds1), stride 36 ----
    float* ds0 = (float*)(smem + SM_DS0);
    float* ds1 = (float*)(smem + SM_DS1);
    const int n_e = (lid & 3) * 2;
    const int r_e = lid >> 2;
    {
        float* dsw = (wid < 4) ? ds0 : ds1;
        const int ol = (wid & 3) * 16 + r_e;
        #pragma unroll
        for (int j = 0; j < 4; j++) {
            *(float2*)(dsw + ol * 36 + j * 8 + n_e)       = make_float2(dacc[j][0], dacc[j][1]);
            *(float2*)(dsw + (ol + 8) * 36 + j * 8 + n_e) = make_float2(dacc[j][2], dacc[j][3]);
        }
    }

    // ---- aggregate u/v halves ----
    if (tid < 64)
        u_s[tid] = g_upart[b * CC + tid] + g_upart[BB * CC + b * CC + tid];
    else if (tid < 128) {
        int cc2 = tid - 64;
        v_s[cc2] = g_vpart[b * CC + cc2] + g_vpart[BB * CC + b * CC + cc2];
    }
    __syncthreads();

    // ---- p/q ----
    {
        const int o = tid & 63, seg = tid >> 6;
        const float* wr = conv_w + o * 128 + seg * 16;
        const float* uu = u_s + seg * 16;
        const float* vv = v_s + seg * 16;
        float ps = 0.f, qs = 0.f;
        #pragma unroll
        for (int i = 0; i < 16; i += 4) {
            float4 w0 = *(const float4*)(wr + i);
            float4 w1 = *(const float4*)(wr + 64 + i);
            float4 u4 = *(const float4*)(uu + i);
            float4 v4 = *(const float4*)(vv + i);
            ps += w0.x * u4.x + w0.y * u4.y + w0.z * u4.z + w0.w * u4.w;
            qs += w1.x * v4.x + w1.y * v4.y + w1.z * v4.z + w1.w * v4.w;
        }
        ppart[seg * 64 + o] = ps;
        qpart[seg * 64 + o] = qs;
    }
    __syncthreads();
    if (tid < 64)
        p_s[tid] = ppart[tid] + ppart[64 + tid] + ppart[128 + tid] + ppart[192 + tid];
    else if (tid < 128) {
        int o = tid - 64;
        q_s[o] = qpart[o] + qpart[64 + o] + qpart[128 + o] + qpart[192 + o];
    }
    __syncthreads();

    // ---- combine (all 8 warps): warp = (o-slice 16, n-half 16) ----
    {
        const int nh = wid >> 2;
        const int obase = (wid & 3) * 16;
        const int o0 = obase + r_e, o1 = o0 + 8;
        const float p0 = p_s[o0], p1 = p_s[o1];
        const float q0 = q_s[o0], q1 = q_s[o1];
        const float c0 = sc_s[o0], c1 = sc_s[o1];
        const float h0 = sh_s[o0], h1 = sh_s[o1];
        float* ob = out + (size_t)(b * CC) * NN + n0;
        #pragma unroll
        for (int j = 0; j < 2; j++) {
            const int n = nh * 16 + j * 8 + n_e;
            float4 m0 = meta[n];
            float4 m1 = meta[n + 1];
            float2 a0 = *(const float2*)(ds0 + o0 * 36 + n);
            float2 a1 = *(const float2*)(ds0 + o1 * 36 + n);
            float2 e0 = *(const float2*)(ds1 + o0 * 36 + n);
            float2 e1 = *(const float2*)(ds1 + o1 * 36 + n);
            float y00 = fmaf(m0.z, e0.x, a0.x);
            y00 = fmaf(p0, m0.x, y00); y00 = fmaf(q0, m0.y, y00);
            float y01 = fmaf(m1.z, e0.y, a0.y);
            y01 = fmaf(p0, m1.x, y01); y01 = fmaf(q0, m1.y, y01);
            float y10 = fmaf(m0.z, e1.x, a1.x);
            y10 = fmaf(p1, m0.x, y10); y10 = fmaf(q1, m0.y, y10);
            float y11 = fmaf(m1.z, e1.y, a1.y);
            y11 = fmaf(p1, m1.x, y11); y11 = fmaf(q1, m1.y, y11);
            y00 = fmaxf(fmaf(y00, c0, h0), 0.f);
            y01 = fmaxf(fmaf(y01, c0, h0), 0.f);
            y10 = fmaxf(fmaf(y10, c1, h1), 0.f);
            y11 = fmaxf(fmaf(y11, c1, h1), 0.f);
            *(float2*)(ob + (size_t)o0 * NN + n) = make_float2(y00, y01);
            *(float2*)(ob + (size_t)o1 * NN + n) = make_float2(y10, y11);
        }
    }
}

// -----------------------------------------------------------------------------
extern "C" void kernel_launch(void* const* d_in, const int* in_sizes, int n_in,
                              void* d_out, int out_size) {
    const float* x      = (const float*)d_in[0];
    const float* w      = (const float*)d_in[1];
    const float* conv_w = (const float*)d_in[2];
    const float* conv_b = (const float*)d_in[3];
    const float* gamma  = (const float*)d_in[4];
    const float* beta   = (const float*)d_in[5];
    const float* mean   = (const float*)d_in[6];
    const float* var    = (const float*)d_in[7];
    float* out = (float*)d_out;

    cudaFuncSetAttribute(k_fused, cudaFuncAttributeMaxDynamicSharedMemorySize, SM_TOTAL);
    k_fused<<<GRID, 256, SM_TOTAL>>>(x, w, conv_w, conv_b, gamma, beta, mean, var, out);
}